// round 2
// baseline (speedup 1.0000x reference)
#include <cuda_runtime.h>
#include <limits.h>

#define PRE 2000
#define POST 300
#define IOU_T 0.55f
#define SCAN_THREADS 512

// Inter-kernel scratch (device globals: allocation-free per harness rules)
__device__ float g_box[PRE * 4];
__device__ float g_score[PRE];
__device__ float g_cls[PRE];
__device__ float g_key[PRE];

// ---------------------------------------------------------------------------
// Kernel 1: sequential WBF scan. One block; all cluster state in shared mem.
// Valid clusters always occupy a compact prefix [0, n_valid), so the
// reference's argmax(match) == min matching cluster index -> atomicMin.
// ---------------------------------------------------------------------------
__global__ void __launch_bounds__(SCAN_THREADS, 1)
wbf_scan(const float* __restrict__ x) {
    extern __shared__ float smem[];
    float4* s_mean = (float4*)smem;               // PRE  (current mean boxes)
    float4* s_sum  = s_mean + PRE;                // PRE  (sum of score*box)
    float*  s_sums = (float*)(s_sum + PRE);       // PRE  (sum of scores)
    float*  s_area = s_sums + PRE;                // PRE  (area of mean box)
    float*  s_cls  = s_area + PRE;                // PRE  (class, float)
    float*  s_x    = s_cls + PRE;                 // PRE*6 (input cached)
    int*    s_cnt  = (int*)(s_x + PRE * 6);       // PRE  (det count)
    int*    ctrl   = s_cnt + PRE;                 // [0]=n_valid [1]=first_match

    const int tid = threadIdx.x;

    // Preload entire input into shared (48 KB): scan loop is global-free.
    for (int i = tid; i < PRE * 6; i += SCAN_THREADS) s_x[i] = x[i];
    if (tid == 0) { ctrl[0] = 0; ctrl[1] = INT_MAX; }
    __syncthreads();

    for (int t = 0; t < PRE; t++) {
        const float bx1 = s_x[t * 6 + 0];
        const float by1 = s_x[t * 6 + 1];
        const float bx2 = s_x[t * 6 + 2];
        const float by2 = s_x[t * 6 + 3];
        const float sc  = s_x[t * 6 + 4];
        const float c   = s_x[t * 6 + 5];
        const float a1  = (bx2 - bx1) * (by2 - by1);
        const int   nv  = ctrl[0];

        // Parallel match search over valid clusters
        for (int i = tid; i < nv; i += SCAN_THREADS) {
            if (s_cls[i] == c) {
                const float4 m = s_mean[i];
                const float lx = fmaxf(bx1, m.x);
                const float ly = fmaxf(by1, m.y);
                const float rx = fminf(bx2, m.z);
                const float ry = fminf(by2, m.w);
                const float w  = fmaxf(rx - lx, 0.0f);
                const float h  = fmaxf(ry - ly, 0.0f);
                const float inter = w * h;
                if (inter > 0.0f) {  // iou==0 otherwise; divide only when needed
                    const float uni = a1 + s_area[i] - inter;
                    // IEEE division to bitwise-match the reference's iou
                    const float iou = (uni > 0.0f) ? __fdiv_rn(inter, uni) : 0.0f;
                    if (iou > IOU_T) atomicMin(&ctrl[1], i);
                }
            }
        }
        __syncthreads();

        // Serial cluster update (thread 0)
        if (tid == 0) {
            const int first = ctrl[1];
            const int idx = (first == INT_MAX) ? nv : first;
            float4 sw; float ss; int cn;
            if (idx == nv) {
                sw = make_float4(0.f, 0.f, 0.f, 0.f); ss = 0.f; cn = 0;
                ctrl[0] = nv + 1;
            } else {
                sw = s_sum[idx]; ss = s_sums[idx]; cn = s_cnt[idx];
            }
            sw.x += sc * bx1; sw.y += sc * by1;
            sw.z += sc * bx2; sw.w += sc * by2;
            ss += sc;
            float4 m;
            m.x = __fdiv_rn(sw.x, ss);
            m.y = __fdiv_rn(sw.y, ss);
            m.z = __fdiv_rn(sw.z, ss);
            m.w = __fdiv_rn(sw.w, ss);
            s_sum[idx]  = sw;
            s_sums[idx] = ss;
            s_mean[idx] = m;
            s_area[idx] = (m.z - m.x) * (m.w - m.y);
            s_cls[idx]  = c;
            s_cnt[idx]  = cn + 1;
            ctrl[1] = INT_MAX;
        }
        __syncthreads();
    }

    // Export final cluster state
    const int nv = ctrl[0];
    for (int i = tid; i < PRE; i += SCAN_THREADS) {
        if (i < nv) {
            const float4 m = s_mean[i];
            g_box[i * 4 + 0] = m.x;
            g_box[i * 4 + 1] = m.y;
            g_box[i * 4 + 2] = m.z;
            g_box[i * 4 + 3] = m.w;
            const float scv = __fdiv_rn(s_sums[i], fmaxf((float)s_cnt[i], 1.0f));
            g_score[i] = scv;
            g_cls[i]   = s_cls[i];
            g_key[i]   = scv;      // valid keys are >= 0.05
        } else {
            g_key[i] = -1.0f;      // invalid sentinel (matches reference)
        }
    }
}

// ---------------------------------------------------------------------------
// Kernel 2: rank-based top-POST selection (stable descending argsort
// semantics). Ranks form a permutation -> each output row written once.
// ---------------------------------------------------------------------------
__global__ void wbf_rank(float* __restrict__ out) {
    __shared__ float k[PRE];
    const int j = blockIdx.x * blockDim.x + threadIdx.x;
    for (int i = threadIdx.x; i < PRE; i += blockDim.x) k[i] = g_key[i];
    __syncthreads();
    if (j >= PRE) return;

    const float kj = k[j];
    int rank = 0;
    #pragma unroll 8
    for (int i = 0; i < PRE; i++) {
        const float ki = k[i];
        rank += (ki > kj) || (ki == kj && i < j);
    }
    if (rank < POST) {
        float* row = out + rank * 6;
        if (kj >= 0.0f) {
            row[0] = g_box[j * 4 + 0];
            row[1] = g_box[j * 4 + 1];
            row[2] = g_box[j * 4 + 2];
            row[3] = g_box[j * 4 + 3];
            row[4] = g_score[j];
            row[5] = g_cls[j];
        } else {
            row[0] = 0.f; row[1] = 0.f; row[2] = 0.f;
            row[3] = 0.f; row[4] = 0.f; row[5] = 0.f;
        }
    }
}

// ---------------------------------------------------------------------------

static const int SCAN_SMEM_BYTES =
    PRE * (int)sizeof(float4) * 2 +   // mean + sum
    PRE * (int)sizeof(float) * 3 +    // sums + area + cls
    PRE * 6 * (int)sizeof(float) +    // cached input
    PRE * (int)sizeof(int) +          // cnt
    2 * (int)sizeof(int);             // ctrl

extern "C" void kernel_launch(void* const* d_in, const int* in_sizes, int n_in,
                              void* d_out, int out_size) {
    const float* x = (const float*)d_in[0];
    float* out = (float*)d_out;

    cudaFuncSetAttribute(wbf_scan,
                         cudaFuncAttributeMaxDynamicSharedMemorySize,
                         SCAN_SMEM_BYTES);

    wbf_scan<<<1, SCAN_THREADS, SCAN_SMEM_BYTES>>>(x);
    wbf_rank<<<(PRE + 255) / 256, 256>>>(out);
}

// round 3
// speedup vs baseline: 1.4391x; 1.4391x over previous
#include <cuda_runtime.h>
#include <limits.h>

#define PRE 2000
#define POST 300
#define IOU_T 0.55f
#define T 512
#define K 4           // cluster slots per thread (T*K >= PRE)
#define ICH 250       // i-chunk for rank partials

// Inter-kernel scratch (device globals: allocation-free per harness rules)
__device__ float g_box[PRE * 4];
__device__ float g_score[PRE];
__device__ float g_cls[PRE];
__device__ float g_key[PRE];
__device__ int   g_rank[PRE];

// ---------------------------------------------------------------------------
// Kernel 1: sequential WBF scan. One block. Cluster mean/area/class held in
// REGISTERS (4 slots per thread); shared memory holds only the running sums
// (read once per step by the single owner thread) and the cached input.
// ONE __syncthreads per step; votes use a 3-slot rotating mailbox so the
// reset never races the reads/writes of adjacent steps.
// ---------------------------------------------------------------------------
__global__ void __launch_bounds__(T, 1)
wbf_scan(const float* __restrict__ x) {
    extern __shared__ float smem[];
    float4* s_sum  = (float4*)smem;             // PRE   sum of score*box
    float*  s_sums = (float*)(s_sum + PRE);     // PRE   sum of scores
    float*  s_cls  = s_sums + PRE;              // PRE   class (export only)
    float*  s_x    = s_cls + PRE;               // PRE*6 cached input
    int*    s_cnt  = (int*)(s_x + PRE * 6);     // PRE   det count
    int*    s_vote = s_cnt + PRE;               // 3     rotating vote slots

    const int tid = threadIdx.x;

    for (int i = tid; i < PRE * 6; i += T) s_x[i] = x[i];
    if (tid < 3) s_vote[tid] = INT_MAX;
    __syncthreads();

    // Register-resident cluster cache: slot i = tid + k*T
    float mx[K], my[K], mz[K], mw[K], ar[K], cl[K];
    int nv = 0;  // tracked consistently by every thread

    // prefetch det 0
    float bx1 = s_x[0], by1 = s_x[1], bx2 = s_x[2], by2 = s_x[3];
    float sc  = s_x[4], cc  = s_x[5];

    for (int t = 0; t < PRE; t++) {
        const float a1 = __fmul_rn(__fsub_rn(bx2, bx1), __fsub_rn(by2, by1));

        // ---- match phase: pure register compute ----
        int vote = INT_MAX;
        #pragma unroll
        for (int k = 0; k < K; k++) {
            const int i = tid + k * T;
            if (i < nv && cl[k] == cc) {
                const float lx = fmaxf(bx1, mx[k]);
                const float ly = fmaxf(by1, my[k]);
                const float rx = fminf(bx2, mz[k]);
                const float ry = fminf(by2, mw[k]);
                const float w  = fmaxf(__fsub_rn(rx, lx), 0.0f);
                const float h  = fmaxf(__fsub_rn(ry, ly), 0.0f);
                const float inter = __fmul_rn(w, h);
                if (inter > 0.0f) {
                    const float uni = __fsub_rn(__fadd_rn(a1, ar[k]), inter);
                    if (uni > 0.0f && __fdiv_rn(inter, uni) > IOU_T)
                        vote = min(vote, i);
                }
            }
        }
        const int slot = t % 3;
        if (vote != INT_MAX) atomicMin(&s_vote[slot], vote);
        __syncthreads();   // the only barrier per step

        // ---- update phase ----
        const int  first = s_vote[slot];
        const bool found = (first != INT_MAX);
        const int  idx   = found ? first : nv;

        // keep this det's values; prefetch next det (hides LDS latency)
        const float ubx1 = bx1, uby1 = by1, ubx2 = bx2, uby2 = by2;
        const float usc = sc, ucc = cc;
        if (t + 1 < PRE) {
            const float* p = &s_x[(t + 1) * 6];
            bx1 = p[0]; by1 = p[1]; bx2 = p[2]; by2 = p[3];
            sc  = p[4]; cc  = p[5];
        }

        // reset the slot used at step t-1; next reused at t+2 (barrier-ordered)
        if (tid == 0) s_vote[(t + 2) % 3] = INT_MAX;

        // only the OWNER thread of cluster idx performs the update
        if ((idx & (T - 1)) == tid) {
            float4 sw; float ss; int cn;
            if (found) {
                sw = s_sum[idx]; ss = s_sums[idx]; cn = s_cnt[idx];
            } else {
                sw = make_float4(0.f, 0.f, 0.f, 0.f); ss = 0.f; cn = 0;
                s_cls[idx] = ucc;
            }
            sw.x = __fadd_rn(sw.x, __fmul_rn(usc, ubx1));
            sw.y = __fadd_rn(sw.y, __fmul_rn(usc, uby1));
            sw.z = __fadd_rn(sw.z, __fmul_rn(usc, ubx2));
            sw.w = __fadd_rn(sw.w, __fmul_rn(usc, uby2));
            ss = __fadd_rn(ss, usc);
            const float nmx = __fdiv_rn(sw.x, ss);
            const float nmy = __fdiv_rn(sw.y, ss);
            const float nmz = __fdiv_rn(sw.z, ss);
            const float nmw = __fdiv_rn(sw.w, ss);
            const float nar = __fmul_rn(__fsub_rn(nmz, nmx), __fsub_rn(nmw, nmy));
            s_sum[idx]  = sw;
            s_sums[idx] = ss;
            s_cnt[idx]  = cn + 1;
            const int kk = idx >> 9;   // idx / T
            #pragma unroll
            for (int k = 0; k < K; k++)
                if (k == kk) {
                    mx[k] = nmx; my[k] = nmy; mz[k] = nmz; mw[k] = nmw;
                    ar[k] = nar; cl[k] = ucc;
                }
        }
        if (!found) nv++;
    }

    // ---- export ----
    __syncthreads();
    for (int i = tid; i < PRE; i += T) {
        if (i < nv) {
            const float4 sw = s_sum[i];
            const float  ss = s_sums[i];
            g_box[i * 4 + 0] = __fdiv_rn(sw.x, ss);
            g_box[i * 4 + 1] = __fdiv_rn(sw.y, ss);
            g_box[i * 4 + 2] = __fdiv_rn(sw.z, ss);
            g_box[i * 4 + 3] = __fdiv_rn(sw.w, ss);
            const float scv = __fdiv_rn(ss, fmaxf((float)s_cnt[i], 1.0f));
            g_score[i] = scv;
            g_cls[i]   = s_cls[i];
            g_key[i]   = scv;          // valid keys >= 0.05
        } else {
            g_key[i] = -1.0f;          // invalid sentinel (matches reference)
        }
        g_rank[i] = 0;
    }
}

// ---------------------------------------------------------------------------
// Kernel 2: partial stable-descending ranks (split over i-chunks for
// parallelism: 8 j-blocks x 8 i-chunks).
// ---------------------------------------------------------------------------
__global__ void wbf_rank_part() {
    __shared__ float kk[ICH];
    const int i0 = blockIdx.y * ICH;
    for (int i = threadIdx.x; i < ICH; i += blockDim.x) kk[i] = g_key[i0 + i];
    __syncthreads();

    const int j = blockIdx.x * blockDim.x + threadIdx.x;
    if (j >= PRE) return;
    const float kj = g_key[j];
    int r = 0;
    #pragma unroll 10
    for (int ii = 0; ii < ICH; ii++) {
        const float ki = kk[ii];
        const int i = i0 + ii;
        r += (ki > kj) || (ki == kj && i < j);
    }
    if (r) atomicAdd(&g_rank[j], r);
}

// ---------------------------------------------------------------------------
// Kernel 3: scatter. Ranks are a permutation -> each output row written once.
// ---------------------------------------------------------------------------
__global__ void wbf_scatter(float* __restrict__ out) {
    const int j = blockIdx.x * blockDim.x + threadIdx.x;
    if (j >= PRE) return;
    const int r = g_rank[j];
    if (r < POST) {
        float* row = out + r * 6;
        if (g_key[j] >= 0.0f) {
            row[0] = g_box[j * 4 + 0];
            row[1] = g_box[j * 4 + 1];
            row[2] = g_box[j * 4 + 2];
            row[3] = g_box[j * 4 + 3];
            row[4] = g_score[j];
            row[5] = g_cls[j];
        } else {
            row[0] = 0.f; row[1] = 0.f; row[2] = 0.f;
            row[3] = 0.f; row[4] = 0.f; row[5] = 0.f;
        }
    }
}

// ---------------------------------------------------------------------------

static const int SCAN_SMEM_BYTES =
    PRE * (int)sizeof(float4) +       // s_sum
    PRE * (int)sizeof(float) * 2 +    // s_sums + s_cls
    PRE * 6 * (int)sizeof(float) +    // s_x
    PRE * (int)sizeof(int) +          // s_cnt
    3 * (int)sizeof(int);             // s_vote

extern "C" void kernel_launch(void* const* d_in, const int* in_sizes, int n_in,
                              void* d_out, int out_size) {
    const float* x = (const float*)d_in[0];
    float* out = (float*)d_out;

    cudaFuncSetAttribute(wbf_scan,
                         cudaFuncAttributeMaxDynamicSharedMemorySize,
                         SCAN_SMEM_BYTES);

    wbf_scan<<<1, T, SCAN_SMEM_BYTES>>>(x);
    wbf_rank_part<<<dim3(8, 8), 256>>>();
    wbf_scatter<<<8, 256>>>(out);
}

// round 4
// speedup vs baseline: 1.5217x; 1.0574x over previous
#include <cuda_runtime.h>
#include <limits.h>

#define PRE 2000
#define POST 300
#define IOU_T 0.55f
#define T 512
#define NC 5
#define ICH 250

// Inter-kernel scratch (device globals: allocation-free per harness rules)
__device__ float g_box[PRE * 4];
__device__ float g_score[PRE];
__device__ float g_cls[PRE];
__device__ float g_key[PRE];
__device__ int   g_rank[PRE];

// ---------------------------------------------------------------------------
// Kernel 1: sequential WBF scan, per-class cluster lists.
// Slot (class c, position p) is owned by thread p; all its state (mean, area,
// weighted sums, count, global index) lives in thread p's registers. Class-c
// global cluster indices are monotone in list position, so the reference's
// "first match" (min global index) == min list position == atomicMin over tid.
// One __syncthreads per step; 3-slot rotating vote mailbox.
// ---------------------------------------------------------------------------

#define MATCH_CASE(C)                                                       \
    if (tid < cntc[C]) {                                                    \
        const float lx = fmaxf(bx1, mx[C]);                                 \
        const float ly = fmaxf(by1, my[C]);                                 \
        const float rx = fminf(bx2, mz[C]);                                 \
        const float ry = fminf(by2, mw[C]);                                 \
        const float w  = fmaxf(__fsub_rn(rx, lx), 0.0f);                    \
        const float h  = fmaxf(__fsub_rn(ry, ly), 0.0f);                    \
        const float inter = __fmul_rn(w, h);                                \
        if (inter > 0.0f) {                                                 \
            const float uni = __fsub_rn(__fadd_rn(a1, ma[C]), inter);       \
            if (uni > 0.0f && __fdiv_rn(inter, uni) > IOU_T) vote = tid;    \
        }                                                                   \
    }

#define UPDATE_CASE(C)                                                      \
    {                                                                       \
        const int p = found ? first : cntc[C];                              \
        if (tid == p) {                                                     \
            if (!found) {                                                   \
                swx[C] = 0.f; swy[C] = 0.f; swz[C] = 0.f; sww[C] = 0.f;     \
                sss[C] = 0.f; sct[C] = 0; gidx[C] = nv;                     \
            }                                                               \
            swx[C] = __fadd_rn(swx[C], __fmul_rn(usc, ubx1));               \
            swy[C] = __fadd_rn(swy[C], __fmul_rn(usc, uby1));               \
            swz[C] = __fadd_rn(swz[C], __fmul_rn(usc, ubx2));               \
            sww[C] = __fadd_rn(sww[C], __fmul_rn(usc, uby2));               \
            sss[C] = __fadd_rn(sss[C], usc);                                \
            sct[C] = sct[C] + 1;                                            \
            mx[C] = __fdiv_rn(swx[C], sss[C]);                              \
            my[C] = __fdiv_rn(swy[C], sss[C]);                              \
            mz[C] = __fdiv_rn(swz[C], sss[C]);                              \
            mw[C] = __fdiv_rn(sww[C], sss[C]);                              \
            ma[C] = __fmul_rn(__fsub_rn(mz[C], mx[C]),                      \
                              __fsub_rn(mw[C], my[C]));                     \
        }                                                                   \
        if (!found) cntc[C]++;                                              \
    }

__global__ void __launch_bounds__(T, 1)
wbf_scan(const float* __restrict__ x) {
    extern __shared__ float smem[];
    float* s_x8   = smem;                      // PRE*8 padded input rows
    int*   s_vote = (int*)(s_x8 + PRE * 8);    // 3 rotating vote slots

    const int tid = threadIdx.x;

    // Preload input, padded to 8-float rows
    for (int i = tid; i < PRE; i += T) {
        const float* src = x + i * 6;
        float* dst = s_x8 + i * 8;
        dst[0] = src[0]; dst[1] = src[1]; dst[2] = src[2];
        dst[3] = src[3]; dst[4] = src[4]; dst[5] = src[5];
    }
    if (tid < 3) s_vote[tid] = INT_MAX;
    __syncthreads();

    // Per-class slot state, all in registers (constant-indexed only)
    float mx[NC], my[NC], mz[NC], mw[NC], ma[NC];
    float swx[NC], swy[NC], swz[NC], sww[NC], sss[NC];
    int   sct[NC], gidx[NC], cntc[NC];
    #pragma unroll
    for (int c = 0; c < NC; c++) { cntc[c] = 0; gidx[c] = -1; }
    int nv = 0;

    // Prefetch det 0
    float bx1 = s_x8[0], by1 = s_x8[1], bx2 = s_x8[2], by2 = s_x8[3];
    float sc  = s_x8[4], cc  = s_x8[5];

    for (int t = 0; t < PRE; t++) {
        const float a1 = __fmul_rn(__fsub_rn(bx2, bx1), __fsub_rn(by2, by1));
        const int ci = (int)cc;

        // ---- match: single register-resident slot per thread ----
        int vote = INT_MAX;
        switch (ci) {
            case 0: MATCH_CASE(0); break;
            case 1: MATCH_CASE(1); break;
            case 2: MATCH_CASE(2); break;
            case 3: MATCH_CASE(3); break;
            default: MATCH_CASE(4); break;
        }
        const int slot = t % 3;
        if (vote != INT_MAX) atomicMin(&s_vote[slot], vote);
        __syncthreads();   // only barrier per step

        // ---- update ----
        const int  first = s_vote[slot];
        const bool found = (first != INT_MAX);

        const float ubx1 = bx1, uby1 = by1, ubx2 = bx2, uby2 = by2;
        const float usc = sc;
        if (t + 1 < PRE) {
            const float* p = s_x8 + (t + 1) * 8;
            bx1 = p[0]; by1 = p[1]; bx2 = p[2]; by2 = p[3];
            sc  = p[4]; cc  = p[5];
        }
        if (tid == 0) s_vote[(t + 2) % 3] = INT_MAX;

        switch (ci) {
            case 0: UPDATE_CASE(0); break;
            case 1: UPDATE_CASE(1); break;
            case 2: UPDATE_CASE(2); break;
            case 3: UPDATE_CASE(3); break;
            default: UPDATE_CASE(4); break;
        }
        if (!found) nv++;
    }

    // ---- export: each slot written once to its global index ----
    #pragma unroll
    for (int c = 0; c < NC; c++) {
        if (gidx[c] >= 0) {
            const int gi = gidx[c];
            g_box[gi * 4 + 0] = mx[c];
            g_box[gi * 4 + 1] = my[c];
            g_box[gi * 4 + 2] = mz[c];
            g_box[gi * 4 + 3] = mw[c];
            const float scv = __fdiv_rn(sss[c], fmaxf((float)sct[c], 1.0f));
            g_score[gi] = scv;
            g_cls[gi]   = (float)c;
            g_key[gi]   = scv;                 // valid keys >= 0.05
        }
    }
    for (int i = nv + tid; i < PRE; i += T) g_key[i] = -1.0f;
    for (int i = tid; i < PRE; i += T) g_rank[i] = 0;
}

// ---------------------------------------------------------------------------
// Kernel 2: partial stable-descending ranks (8 j-blocks x 8 i-chunks)
// ---------------------------------------------------------------------------
__global__ void wbf_rank_part() {
    __shared__ float kk[ICH];
    const int i0 = blockIdx.y * ICH;
    for (int i = threadIdx.x; i < ICH; i += blockDim.x) kk[i] = g_key[i0 + i];
    __syncthreads();

    const int j = blockIdx.x * blockDim.x + threadIdx.x;
    if (j >= PRE) return;
    const float kj = g_key[j];
    int r = 0;
    #pragma unroll 10
    for (int ii = 0; ii < ICH; ii++) {
        const float ki = kk[ii];
        const int i = i0 + ii;
        r += (ki > kj) || (ki == kj && i < j);
    }
    if (r) atomicAdd(&g_rank[j], r);
}

// ---------------------------------------------------------------------------
// Kernel 3: scatter (ranks are a permutation -> each row written once)
// ---------------------------------------------------------------------------
__global__ void wbf_scatter(float* __restrict__ out) {
    const int j = blockIdx.x * blockDim.x + threadIdx.x;
    if (j >= PRE) return;
    const int r = g_rank[j];
    if (r < POST) {
        float* row = out + r * 6;
        if (g_key[j] >= 0.0f) {
            row[0] = g_box[j * 4 + 0];
            row[1] = g_box[j * 4 + 1];
            row[2] = g_box[j * 4 + 2];
            row[3] = g_box[j * 4 + 3];
            row[4] = g_score[j];
            row[5] = g_cls[j];
        } else {
            row[0] = 0.f; row[1] = 0.f; row[2] = 0.f;
            row[3] = 0.f; row[4] = 0.f; row[5] = 0.f;
        }
    }
}

// ---------------------------------------------------------------------------

static const int SCAN_SMEM_BYTES = PRE * 8 * (int)sizeof(float) + 4 * (int)sizeof(int);

extern "C" void kernel_launch(void* const* d_in, const int* in_sizes, int n_in,
                              void* d_out, int out_size) {
    const float* x = (const float*)d_in[0];
    float* out = (float*)d_out;

    cudaFuncSetAttribute(wbf_scan,
                         cudaFuncAttributeMaxDynamicSharedMemorySize,
                         SCAN_SMEM_BYTES);

    wbf_scan<<<1, T, SCAN_SMEM_BYTES>>>(x);
    wbf_rank_part<<<dim3(8, 8), 256>>>();
    wbf_scatter<<<8, 256>>>(out);
}

// round 5
// speedup vs baseline: 5.2393x; 3.4430x over previous
#include <cuda_runtime.h>
#include <limits.h>

#define PRE 2000
#define POST 300
#define IOU_T 0.55f
#define T 512
#define NC 5
#define CAP 512          // per-class cluster capacity (max class count ~430)
#define W 16             // speculation window = one warp per window det
#define ICH 250

// Inter-kernel scratch (device globals: allocation-free per harness rules)
__device__ float g_box[PRE * 4];
__device__ float g_score[PRE];
__device__ float g_cls[PRE];
__device__ float g_key[PRE];
__device__ int   g_rank[PRE];

// ---------------------------------------------------------------------------
// Kernel 1: speculative-window WBF scan.
// Per round: warp w evaluates window det (t0+w) against its class's cluster
// list AND against earlier window dets as singleton clusters. j* = first det
// with any match. Dets < j* are committed as parallel appends (reference-
// identical), det j* is merged serially (its candidate state was unchanged),
// and the next round restarts at j*+1. First-match index is exact:
//   - within a class list, global index is monotone in list position
//   - every pre-existing cluster's global index < any window singleton's
// ---------------------------------------------------------------------------
__global__ void __launch_bounds__(T, 1)
wbf_scan(const float* __restrict__ x) {
    extern __shared__ float smem[];
    float*  s_x     = smem;                        // PRE*6 cached input
    float4* cl_mean = (float4*)(s_x + PRE * 6);    // NC*CAP current means
    float4* cl_sum  = cl_mean + NC * CAP;          // NC*CAP weighted sums
    float*  cl_area = (float*)(cl_sum + NC * CAP); // NC*CAP mean-box areas
    float*  cl_sums = cl_area + NC * CAP;          // NC*CAP score sums
    int*    cl_cnt  = (int*)(cl_sums + NC * CAP);  // NC*CAP det counts
    int*    cl_gid  = cl_cnt + NC * CAP;           // NC*CAP global indices

    __shared__ int s_cntc[NC];
    __shared__ int s_t0, s_nv;
    __shared__ int m_ext[W], m_int[W];

    const int tid  = threadIdx.x;
    const int wrp  = tid >> 5;
    const int lane = tid & 31;

    for (int i = tid; i < PRE * 6; i += T) s_x[i] = x[i];
    if (tid < NC) s_cntc[tid] = 0;
    if (tid == 0) { s_t0 = 0; s_nv = 0; }
    __syncthreads();

    while (true) {
        const int t0 = s_t0;
        if (t0 >= PRE) break;
        const int nv = s_nv;

        // ================= phase A: match evaluation =================
        const int t = t0 + wrp;
        if (t < PRE) {
            const float* d = s_x + t * 6;
            const float bx1 = d[0], by1 = d[1], bx2 = d[2], by2 = d[3];
            const float cc = d[5];
            const float a1 = __fmul_rn(__fsub_rn(bx2, bx1), __fsub_rn(by2, by1));
            const int ci  = (int)cc;
            const int nvc = s_cntc[ci];

            int extMin = INT_MAX;
            for (int p = lane; p < nvc; p += 32) {
                const float4 m  = cl_mean[ci * CAP + p];
                const float  a2 = cl_area[ci * CAP + p];
                const float lx = fmaxf(bx1, m.x);
                const float ly = fmaxf(by1, m.y);
                const float rx = fminf(bx2, m.z);
                const float ry = fminf(by2, m.w);
                const float ww = fmaxf(__fsub_rn(rx, lx), 0.0f);
                const float hh = fmaxf(__fsub_rn(ry, ly), 0.0f);
                const float inter = __fmul_rn(ww, hh);
                if (inter > 0.0f) {
                    const float uni = __fsub_rn(__fadd_rn(a1, a2), inter);
                    if (__fdiv_rn(inter, uni) > IOU_T) extMin = min(extMin, p);
                }
            }

            int intraMin = INT_MAX;
            if (lane < wrp) {   // earlier window det as singleton cluster
                const float* di = s_x + (t0 + lane) * 6;
                if (di[5] == cc) {
                    const float s  = di[4];
                    const float mx = __fdiv_rn(__fmul_rn(s, di[0]), s);
                    const float my = __fdiv_rn(__fmul_rn(s, di[1]), s);
                    const float mz = __fdiv_rn(__fmul_rn(s, di[2]), s);
                    const float mw = __fdiv_rn(__fmul_rn(s, di[3]), s);
                    const float a2 = __fmul_rn(__fsub_rn(mz, mx), __fsub_rn(mw, my));
                    const float lx = fmaxf(bx1, mx);
                    const float ly = fmaxf(by1, my);
                    const float rx = fminf(bx2, mz);
                    const float ry = fminf(by2, mw);
                    const float ww = fmaxf(__fsub_rn(rx, lx), 0.0f);
                    const float hh = fmaxf(__fsub_rn(ry, ly), 0.0f);
                    const float inter = __fmul_rn(ww, hh);
                    if (inter > 0.0f) {
                        const float uni = __fsub_rn(__fadd_rn(a1, a2), inter);
                        if (__fdiv_rn(inter, uni) > IOU_T) intraMin = lane;
                    }
                }
            }
            extMin   = __reduce_min_sync(0xffffffffu, extMin);
            intraMin = __reduce_min_sync(0xffffffffu, intraMin);
            if (lane == 0) { m_ext[wrp] = extMin; m_int[wrp] = intraMin; }
        }
        __syncthreads();

        // ================= phase B: commit (warp 0) =================
        if (wrp == 0) {
            const int W_eff = min(W, PRE - t0);
            const bool matched = (lane < W_eff) &&
                (m_ext[lane] != INT_MAX || m_int[lane] != INT_MAX);
            const unsigned mmask = __ballot_sync(0xffffffffu, matched);
            const int jstar = mmask ? (__ffs(mmask) - 1) : W_eff;

            // parallel appends for dets < jstar
            const bool app = lane < jstar;
            const int  mci = app ? (int)s_x[(t0 + lane) * 6 + 5] : (NC + lane);
            const unsigned same = __match_any_sync(0xffffffffu, mci);
            int myslot = -1;
            if (app) {
                const int off  = __popc(same & ((1u << lane) - 1));
                const int slot = s_cntc[mci] + off;
                myslot = slot;
                const float* d = s_x + (t0 + lane) * 6;
                const float s = d[4];
                float4 sw;
                sw.x = __fmul_rn(s, d[0]); sw.y = __fmul_rn(s, d[1]);
                sw.z = __fmul_rn(s, d[2]); sw.w = __fmul_rn(s, d[3]);
                const int base = mci * CAP + slot;
                cl_sum[base]  = sw;
                cl_sums[base] = s;
                cl_cnt[base]  = 1;
                cl_gid[base]  = nv + lane;
                float4 m;
                m.x = __fdiv_rn(sw.x, s); m.y = __fdiv_rn(sw.y, s);
                m.z = __fdiv_rn(sw.z, s); m.w = __fdiv_rn(sw.w, s);
                cl_mean[base] = m;
                cl_area[base] = __fmul_rn(__fsub_rn(m.z, m.x), __fsub_rn(m.w, m.y));
            }
            __syncwarp();
            if (app && lane == __ffs(same) - 1) s_cntc[mci] += __popc(same);

            // serial merge of det jstar (if any)
            const int intr = (jstar < W_eff) ? m_int[jstar] : 0;
            const int islot = __shfl_sync(0xffffffffu, myslot, intr & 31);
            if (lane == 0) {
                if (jstar < W_eff) {
                    const float* d = s_x + (t0 + jstar) * 6;
                    const int ci  = (int)d[5];
                    const int ext = m_ext[jstar];
                    const int slot = (ext != INT_MAX) ? ext : islot;
                    const int base = ci * CAP + slot;
                    float4 sw = cl_sum[base];
                    float  ss = cl_sums[base];
                    const int cn = cl_cnt[base];
                    const float s = d[4];
                    sw.x = __fadd_rn(sw.x, __fmul_rn(s, d[0]));
                    sw.y = __fadd_rn(sw.y, __fmul_rn(s, d[1]));
                    sw.z = __fadd_rn(sw.z, __fmul_rn(s, d[2]));
                    sw.w = __fadd_rn(sw.w, __fmul_rn(s, d[3]));
                    ss = __fadd_rn(ss, s);
                    cl_sum[base]  = sw;
                    cl_sums[base] = ss;
                    cl_cnt[base]  = cn + 1;
                    float4 m;
                    m.x = __fdiv_rn(sw.x, ss); m.y = __fdiv_rn(sw.y, ss);
                    m.z = __fdiv_rn(sw.z, ss); m.w = __fdiv_rn(sw.w, ss);
                    cl_mean[base] = m;
                    cl_area[base] = __fmul_rn(__fsub_rn(m.z, m.x),
                                              __fsub_rn(m.w, m.y));
                    s_t0 = t0 + jstar + 1;
                    s_nv = nv + jstar;
                } else {
                    s_t0 = t0 + W_eff;
                    s_nv = nv + W_eff;
                }
            }
        }
        __syncthreads();
    }

    // ================= export =================
    for (int idx = tid; idx < NC * CAP; idx += T) {
        const int c = idx / CAP, p = idx - c * CAP;
        if (p < s_cntc[c]) {
            const int gi = cl_gid[idx];
            const float4 m = cl_mean[idx];
            g_box[gi * 4 + 0] = m.x;
            g_box[gi * 4 + 1] = m.y;
            g_box[gi * 4 + 2] = m.z;
            g_box[gi * 4 + 3] = m.w;
            const float scv = __fdiv_rn(cl_sums[idx],
                                        fmaxf((float)cl_cnt[idx], 1.0f));
            g_score[gi] = scv;
            g_cls[gi]   = (float)c;
            g_key[gi]   = scv;            // valid keys >= 0.05
        }
    }
    const int nvf = s_nv;
    for (int i = nvf + tid; i < PRE; i += T) g_key[i] = -1.0f;
    for (int i = tid; i < PRE; i += T) g_rank[i] = 0;
}

// ---------------------------------------------------------------------------
// Kernel 2: partial stable-descending ranks (8 j-blocks x 8 i-chunks)
// ---------------------------------------------------------------------------
__global__ void wbf_rank_part() {
    __shared__ float kk[ICH];
    const int i0 = blockIdx.y * ICH;
    for (int i = threadIdx.x; i < ICH; i += blockDim.x) kk[i] = g_key[i0 + i];
    __syncthreads();

    const int j = blockIdx.x * blockDim.x + threadIdx.x;
    if (j >= PRE) return;
    const float kj = g_key[j];
    int r = 0;
    #pragma unroll 10
    for (int ii = 0; ii < ICH; ii++) {
        const float ki = kk[ii];
        const int i = i0 + ii;
        r += (ki > kj) || (ki == kj && i < j);
    }
    if (r) atomicAdd(&g_rank[j], r);
}

// ---------------------------------------------------------------------------
// Kernel 3: scatter (ranks are a permutation -> each row written once)
// ---------------------------------------------------------------------------
__global__ void wbf_scatter(float* __restrict__ out) {
    const int j = blockIdx.x * blockDim.x + threadIdx.x;
    if (j >= PRE) return;
    const int r = g_rank[j];
    if (r < POST) {
        float* row = out + r * 6;
        if (g_key[j] >= 0.0f) {
            row[0] = g_box[j * 4 + 0];
            row[1] = g_box[j * 4 + 1];
            row[2] = g_box[j * 4 + 2];
            row[3] = g_box[j * 4 + 3];
            row[4] = g_score[j];
            row[5] = g_cls[j];
        } else {
            row[0] = 0.f; row[1] = 0.f; row[2] = 0.f;
            row[3] = 0.f; row[4] = 0.f; row[5] = 0.f;
        }
    }
}

// ---------------------------------------------------------------------------

static const int SCAN_SMEM_BYTES =
    PRE * 6 * (int)sizeof(float) +          // s_x
    NC * CAP * (int)sizeof(float4) * 2 +    // cl_mean + cl_sum
    NC * CAP * (int)sizeof(float) * 2 +     // cl_area + cl_sums
    NC * CAP * (int)sizeof(int) * 2;        // cl_cnt + cl_gid

extern "C" void kernel_launch(void* const* d_in, const int* in_sizes, int n_in,
                              void* d_out, int out_size) {
    const float* x = (const float*)d_in[0];
    float* out = (float*)d_out;

    cudaFuncSetAttribute(wbf_scan,
                         cudaFuncAttributeMaxDynamicSharedMemorySize,
                         SCAN_SMEM_BYTES);

    wbf_scan<<<1, T, SCAN_SMEM_BYTES>>>(x);
    wbf_rank_part<<<dim3(8, 8), 256>>>();
    wbf_scatter<<<8, 256>>>(out);
}

// round 7
// speedup vs baseline: 5.6525x; 1.0789x over previous
#include <cuda_runtime.h>
#include <limits.h>

#define PRE 2000
#define POST 300
#define IOU_T 0.55f
#define T 512
#define NC 5
#define SLOTS 4
#define OVF (SLOTS + 1)
#define ICH 250

// Inter-kernel scratch (device globals: allocation-free per harness rules)
__device__ float g_box[PRE * 4];
__device__ float g_score[PRE];
__device__ float g_cls[PRE];
__device__ float g_key[PRE];
__device__ int   g_rank[PRE];

// Exact reference IoU decision: det box (bx*, a1) vs cluster mean (m*, a2).
__device__ __forceinline__ bool iou_match(
    float bx1, float by1, float bx2, float by2, float a1,
    float mx, float my, float mz, float mw, float a2)
{
    const float lx = fmaxf(bx1, mx);
    const float ly = fmaxf(by1, my);
    const float rx = fminf(bx2, mz);
    const float ry = fminf(by2, mw);
    const float w  = fmaxf(__fsub_rn(rx, lx), 0.0f);
    const float h  = fmaxf(__fsub_rn(ry, ly), 0.0f);
    const float inter = __fmul_rn(w, h);
    if (inter <= 0.0f) return false;
    const float uni = __fsub_rn(__fadd_rn(a1, a2), inter);  // >= inter > 0
    return __fdiv_rn(inter, uni) > IOU_T;
}

// ---------------------------------------------------------------------------
// Kernel 1: epoch-based WBF.
//   Every det starts as a singleton cluster keyed by its creator index.
//   Phase 1 precomputes, for each det, all matching creators (vs singleton
//   means) -- exact until a merge occurs. Phase 2 finds the earliest merger
//   t1 (creators in [cur,t1) are provably alive), merges it, and repairs
//   only the affected cluster's match bits. One epoch per merge.
// ---------------------------------------------------------------------------
__global__ void __launch_bounds__(T, 1)
wbf_scan(const float* __restrict__ x) {
    extern __shared__ float smem[];
    float4* s_mean = (float4*)smem;                    // PRE current means
    float4* s_sum  = s_mean + PRE;                     // PRE weighted sums
    float*  s_x    = (float*)(s_sum + PRE);            // PRE*6 input
    float*  s_area = s_x + PRE * 6;                    // PRE mean areas
    float*  s_ss   = s_area + PRE;                     // PRE score sums
    int*    s_cnt  = (int*)(s_ss + PRE);               // PRE det counts
    int*    s_ent  = s_cnt + PRE;                      // PRE*SLOTS creators
    int*    s_nent = s_ent + PRE * SLOTS;              // PRE entry counts
    int*    s_clsi = s_nent + PRE;                     // PRE class-ordered det ids
    int*    s_cand = s_clsi + PRE;                     // PRE candidate det ids
    unsigned char* s_merged = (unsigned char*)(s_cand + PRE); // PRE
    unsigned char* s_inc    = s_merged + PRE;                 // PRE

    __shared__ int s_off[NC], s_ccnt[NC];
    __shared__ int s_t1, s_cstar, s_ncand, s_cur;
    __shared__ float s_bc[5];

    const int tid  = threadIdx.x;
    const int wrp  = tid >> 5;
    const int lane = tid & 31;

    for (int i = tid; i < PRE * 6; i += T) s_x[i] = x[i];
    if (tid == 0) { s_ncand = 0; s_cur = 0; }
    __syncthreads();

    // ---- init all dets as singleton clusters (exact reference state) ----
    for (int i = tid; i < PRE; i += T) {
        const float* d = s_x + i * 6;
        const float s = d[4];
        float4 sw;
        sw.x = __fmul_rn(s, d[0]); sw.y = __fmul_rn(s, d[1]);
        sw.z = __fmul_rn(s, d[2]); sw.w = __fmul_rn(s, d[3]);
        s_sum[i] = sw; s_ss[i] = s; s_cnt[i] = 1;
        float4 m;
        m.x = __fdiv_rn(sw.x, s); m.y = __fdiv_rn(sw.y, s);
        m.z = __fdiv_rn(sw.z, s); m.w = __fdiv_rn(sw.w, s);
        s_mean[i] = m;
        s_area[i] = __fmul_rn(__fsub_rn(m.z, m.x), __fsub_rn(m.w, m.y));
        s_merged[i] = 0;
    }

    // ---- stable class bucketing (warp 0, ballot-based) ----
    if (wrp == 0) {
        int cnt[NC];
        #pragma unroll
        for (int c = 0; c < NC; c++) cnt[c] = 0;
        for (int g = 0; g < PRE; g += 32) {
            const int i = g + lane;
            const int ci = (i < PRE) ? (int)s_x[i * 6 + 5] : -1;
            #pragma unroll
            for (int c = 0; c < NC; c++)
                cnt[c] += __popc(__ballot_sync(0xffffffffu, ci == c));
        }
        int off[NC];
        off[0] = 0;
        #pragma unroll
        for (int c = 1; c < NC; c++) off[c] = off[c - 1] + cnt[c - 1];
        if (lane < NC) { s_off[lane] = off[lane]; s_ccnt[lane] = cnt[lane]; }
        int run[NC];
        #pragma unroll
        for (int c = 0; c < NC; c++) run[c] = 0;
        for (int g = 0; g < PRE; g += 32) {
            const int i = g + lane;
            const int ci = (i < PRE) ? (int)s_x[i * 6 + 5] : -1;
            #pragma unroll
            for (int c = 0; c < NC; c++) {
                const unsigned m = __ballot_sync(0xffffffffu, ci == c);
                if (ci == c)
                    s_clsi[off[c] + run[c] + __popc(m & ((1u << lane) - 1u))] = i;
                run[c] += __popc(m);
            }
        }
    }
    __syncthreads();

    // ---- phase 1: all same-class pairs (a < b), b's across lanes ----
    for (int c = 0; c < NC; c++) {
        const int off = s_off[c], n = s_ccnt[c];
        const int ntile = (n + 31) >> 5;
        for (int tile = wrp; tile < ntile; tile += (T / 32)) {
            const int bi = tile * 32 + lane;
            const bool act = bi < n;
            int b = 0;
            float bx1 = 0, by1 = 0, bx2 = 0, by2 = 0, a1 = 0;
            if (act) {
                b = s_clsi[off + bi];
                const float* d = s_x + b * 6;
                bx1 = d[0]; by1 = d[1]; bx2 = d[2]; by2 = d[3];
                a1 = __fmul_rn(__fsub_rn(bx2, bx1), __fsub_rn(by2, by1));
            }
            int ne = 0;
            const int hi = min(n, tile * 32 + 32);
            for (int ai = 0; ai < hi; ai++) {
                const int a = s_clsi[off + ai];          // broadcast LDS
                const float4 mm = s_mean[a];             // broadcast LDS
                const float  a2 = s_area[a];             // broadcast LDS
                if (act && ai < bi &&
                    iou_match(bx1, by1, bx2, by2, a1, mm.x, mm.y, mm.z, mm.w, a2)) {
                    if (ne < SLOTS) s_ent[b * SLOTS + ne] = a;
                    ne++;
                }
            }
            if (act) s_nent[b] = (ne > SLOTS) ? OVF : ne;
        }
    }
    __syncthreads();

    // ---- candidate compaction ----
    for (int i = tid; i < PRE; i += T) {
        if (s_nent[i] > 0) {
            const int p = atomicAdd(&s_ncand, 1);
            s_cand[p] = i;
            s_inc[i] = 1;
        } else s_inc[i] = 0;
    }
    __syncthreads();

    // full rescan fallback (overflowed lists only; probability ~0)
    auto full_rescan = [&](int t, int cur) -> int {
        const float* d = s_x + t * 6;
        const float bx1 = d[0], by1 = d[1], bx2 = d[2], by2 = d[3];
        const float a1 = __fmul_rn(__fsub_rn(bx2, bx1), __fsub_rn(by2, by1));
        const int ci = (int)d[5];
        const int off = s_off[ci], n = s_ccnt[ci];
        for (int k = 0; k < n; k++) {
            const int a = s_clsi[off + k];
            if (a >= t) break;
            if (a < cur && s_merged[a]) continue;
            const float4 mm = s_mean[a];
            if (iou_match(bx1, by1, bx2, by2, a1, mm.x, mm.y, mm.z, mm.w, s_area[a]))
                return a;
        }
        return INT_MAX;
    };

    // ---- phase 2: one epoch per merge ----
    while (true) {
        if (tid == 0) s_t1 = INT_MAX;
        __syncthreads();
        const int cur = s_cur;
        const int ncand = s_ncand;

        int lmin = INT_MAX;
        for (int q = tid; q < ncand; q += T) {
            const int t = s_cand[q];
            if (t < cur || t >= lmin) continue;
            const int ne = s_nent[t];
            bool has = false;
            if (ne == OVF) {
                has = (full_rescan(t, cur) != INT_MAX);
            } else {
                for (int e = 0; e < ne; e++) {
                    const int a = s_ent[t * SLOTS + e];
                    if (a >= cur || !s_merged[a]) { has = true; break; }
                }
            }
            if (has) lmin = t;
        }
        if (lmin != INT_MAX) atomicMin(&s_t1, lmin);
        __syncthreads();

        const int t1 = s_t1;
        if (t1 == INT_MAX) break;

        if (tid == 0) {
            // first match = min alive creator
            int cs = INT_MAX;
            const int ne = s_nent[t1];
            if (ne == OVF) {
                cs = full_rescan(t1, cur);
            } else {
                for (int e = 0; e < ne; e++) {
                    const int a = s_ent[t1 * SLOTS + e];
                    if (a >= cur || !s_merged[a]) cs = min(cs, a);
                }
            }
            // merge det t1 into cluster cs (reference-exact arithmetic)
            const float* d = s_x + t1 * 6;
            const float s = d[4];
            float4 sw = s_sum[cs];
            float  ss = s_ss[cs];
            sw.x = __fadd_rn(sw.x, __fmul_rn(s, d[0]));
            sw.y = __fadd_rn(sw.y, __fmul_rn(s, d[1]));
            sw.z = __fadd_rn(sw.z, __fmul_rn(s, d[2]));
            sw.w = __fadd_rn(sw.w, __fmul_rn(s, d[3]));
            ss = __fadd_rn(ss, s);
            s_sum[cs] = sw; s_ss[cs] = ss; s_cnt[cs] += 1;
            float4 m;
            m.x = __fdiv_rn(sw.x, ss); m.y = __fdiv_rn(sw.y, ss);
            m.z = __fdiv_rn(sw.z, ss); m.w = __fdiv_rn(sw.w, ss);
            s_mean[cs] = m;
            const float na = __fmul_rn(__fsub_rn(m.z, m.x), __fsub_rn(m.w, m.y));
            s_area[cs] = na;
            s_merged[t1] = 1;
            s_cur = t1 + 1;
            s_cstar = cs;
            s_bc[0] = m.x; s_bc[1] = m.y; s_bc[2] = m.z; s_bc[3] = m.w; s_bc[4] = na;
        }
        __syncthreads();

        // repair: recheck all later same-class dets vs cstar's new mean
        const int cs = s_cstar;
        const int ci = (int)s_x[cs * 6 + 5];
        const float mx = s_bc[0], my = s_bc[1], mz = s_bc[2], mw = s_bc[3];
        const float a2 = s_bc[4];
        const int off = s_off[ci], n = s_ccnt[ci];
        for (int k = tid; k < n; k += T) {
            const int t = s_clsi[off + k];
            if (t <= t1) continue;
            const int ne = s_nent[t];
            if (ne == OVF) continue;                 // ovf dets always rescan
            const float* d = s_x + t * 6;
            const float bx1 = d[0], by1 = d[1], bx2 = d[2], by2 = d[3];
            const float a1 = __fmul_rn(__fsub_rn(bx2, bx1), __fsub_rn(by2, by1));
            const bool match = iou_match(bx1, by1, bx2, by2, a1, mx, my, mz, mw, a2);
            int fe = -1;
            for (int e = 0; e < ne; e++)
                if (s_ent[t * SLOTS + e] == cs) { fe = e; break; }
            if (match && fe < 0) {
                if (ne < SLOTS) { s_ent[t * SLOTS + ne] = cs; s_nent[t] = ne + 1; }
                else s_nent[t] = OVF;
                if (!s_inc[t]) {
                    s_inc[t] = 1;
                    const int p = atomicAdd(&s_ncand, 1);
                    s_cand[p] = t;
                }
            } else if (!match && fe >= 0) {
                s_ent[t * SLOTS + fe] = s_ent[t * SLOTS + ne - 1];
                s_nent[t] = ne - 1;
            }
        }
        __syncthreads();
    }

    // ---- export (det-indexed; alive order == reference cluster order) ----
    for (int i = tid; i < PRE; i += T) {
        if (!s_merged[i]) {
            const float4 m = s_mean[i];
            g_box[i * 4 + 0] = m.x;
            g_box[i * 4 + 1] = m.y;
            g_box[i * 4 + 2] = m.z;
            g_box[i * 4 + 3] = m.w;
            const float scv = __fdiv_rn(s_ss[i], fmaxf((float)s_cnt[i], 1.0f));
            g_score[i] = scv;
            g_cls[i]   = s_x[i * 6 + 5];
            g_key[i]   = scv;          // valid keys >= 0.05
        } else {
            g_key[i] = -1.0f;          // invalid sentinel (matches reference)
        }
        g_rank[i] = 0;
    }
}

// ---------------------------------------------------------------------------
// Kernel 2: partial stable-descending ranks (8 j-blocks x 8 i-chunks)
// ---------------------------------------------------------------------------
__global__ void wbf_rank_part() {
    __shared__ float kk[ICH];
    const int i0 = blockIdx.y * ICH;
    for (int i = threadIdx.x; i < ICH; i += blockDim.x) kk[i] = g_key[i0 + i];
    __syncthreads();

    const int j = blockIdx.x * blockDim.x + threadIdx.x;
    if (j >= PRE) return;
    const float kj = g_key[j];
    int r = 0;
    #pragma unroll 10
    for (int ii = 0; ii < ICH; ii++) {
        const float ki = kk[ii];
        const int i = i0 + ii;
        r += (ki > kj) || (ki == kj && i < j);
    }
    if (r) atomicAdd(&g_rank[j], r);
}

// ---------------------------------------------------------------------------
// Kernel 3: scatter (ranks are a permutation -> each row written once)
// ---------------------------------------------------------------------------
__global__ void wbf_scatter(float* __restrict__ out) {
    const int j = blockIdx.x * blockDim.x + threadIdx.x;
    if (j >= PRE) return;
    const int r = g_rank[j];
    if (r < POST) {
        float* row = out + r * 6;
        if (g_key[j] >= 0.0f) {
            row[0] = g_box[j * 4 + 0];
            row[1] = g_box[j * 4 + 1];
            row[2] = g_box[j * 4 + 2];
            row[3] = g_box[j * 4 + 3];
            row[4] = g_score[j];
            row[5] = g_cls[j];
        } else {
            row[0] = 0.f; row[1] = 0.f; row[2] = 0.f;
            row[3] = 0.f; row[4] = 0.f; row[5] = 0.f;
        }
    }
}

// ---------------------------------------------------------------------------

static const int SCAN_SMEM_BYTES =
    PRE * (int)sizeof(float4) * 2 +       // s_mean + s_sum
    PRE * 6 * (int)sizeof(float) +        // s_x
    PRE * (int)sizeof(float) * 2 +        // s_area + s_ss
    PRE * (int)sizeof(int) +              // s_cnt
    PRE * SLOTS * (int)sizeof(int) +      // s_ent
    PRE * (int)sizeof(int) * 3 +          // s_nent + s_clsi + s_cand
    PRE * 2;                              // s_merged + s_inc

extern "C" void kernel_launch(void* const* d_in, const int* in_sizes, int n_in,
                              void* d_out, int out_size) {
    const float* x = (const float*)d_in[0];
    float* out = (float*)d_out;

    cudaFuncSetAttribute(wbf_scan,
                         cudaFuncAttributeMaxDynamicSharedMemorySize,
                         SCAN_SMEM_BYTES);

    wbf_scan<<<1, T, SCAN_SMEM_BYTES>>>(x);
    wbf_rank_part<<<dim3(8, 8), 256>>>();
    wbf_scatter<<<8, 256>>>(out);
}